// round 11
// baseline (speedup 1.0000x reference)
#include <cuda_runtime.h>

#define CEPS 1e-3f
#define NPMAX 100352
#define WSTRIDE 264   // padded k-stride for Ws: 1056B -> k,k' conflict only if k==k' mod 4

// scratch (allocation-free rule: __device__ globals)
__device__ float g_y0[NPMAX * 16];
__device__ float g_y0b[NPMAX * 16];
__device__ float g_y1[NPMAX * 16];
__device__ float g_merged[200000 * 16];
__device__ float g_stats[64];     // [0:16) sum0, [16:32) sq0, [32:48) sum1, [48:64) sq1
__device__ int   g_pairs[27 * NPMAX];  // slot-major packed (k<<20 | id)
__device__ int   g_rowof[NPMAX];       // sorted pos -> original row n
__device__ int   g_cnt[NPMAX];         // per original row: # valid neighbors
__device__ int   g_pcnt[NPMAX];        // per sorted pos: # valid neighbors
__device__ int   g_blkcnt[512 * 28];
__device__ int   g_blkbase[512 * 28];
__device__ int   g_clsoff[28];

// ---------------------------------------------------------------------------
// Pass 1: per-row valid-neighbor count + per-(block,bucket) histogram.
// Bucket = 27 - cnt  (descending counts first -> heavy blocks scheduled early).
// ---------------------------------------------------------------------------
__global__ __launch_bounds__(256) void count_kernel(
    const int* __restrict__ nbr, int N)
{
    __shared__ int snbr[256 * 27];
    __shared__ int hist[28];
    int tid = threadIdx.x;
    int n0 = blockIdx.x * 256;
    int lim = (N - n0) * 27;
    for (int i = tid; i < 256 * 27; i += 256)
        snbr[i] = (i < lim) ? nbr[n0 * 27 + i] : -1;
    if (tid < 28) hist[tid] = 0;
    __syncthreads();
    int n = n0 + tid;
    if (n < N) {
        int c = 0;
#pragma unroll
        for (int k = 0; k < 27; k++) c += (snbr[tid * 27 + k] >= 0);
        g_cnt[n] = c;
        atomicAdd(&hist[27 - c], 1);
    }
    __syncthreads();
    if (tid < 28) g_blkcnt[blockIdx.x * 28 + tid] = hist[tid];
}

// Pass 2: two-level prefix (lane = bucket): block bases + bucket offsets.
__global__ void prefix_kernel(int nblk)
{
    int lane = threadIdx.x;
    int run = 0;
    if (lane < 28) {
        for (int b = 0; b < nblk; b++) {
            int c = g_blkcnt[b * 28 + lane];
            g_blkbase[b * 28 + lane] = run;
            run += c;
        }
    }
    int off = 0;
    for (int j = 0; j < 28; j++) {
        int v = __shfl_sync(0xffffffffu, run, j);
        if (j < lane) off += v;
    }
    if (lane < 28) g_clsoff[lane] = off;
}

// Pass 3: scatter rows to sorted positions; emit packed CSR pairs slot-major.
__global__ __launch_bounds__(256) void build_kernel(
    const int* __restrict__ nbr, int N, int NP)
{
    __shared__ int snbr[256 * 27];
    __shared__ int base[28];
    int tid = threadIdx.x;
    int n0 = blockIdx.x * 256;
    int lim = (N - n0) * 27;
    for (int i = tid; i < 256 * 27; i += 256)
        snbr[i] = (i < lim) ? nbr[n0 * 27 + i] : -1;
    if (tid < 28) base[tid] = g_clsoff[tid] + g_blkbase[blockIdx.x * 28 + tid];
    __syncthreads();
    int n = n0 + tid;
    if (n < N) {
        int c = g_cnt[n];
        int pos = atomicAdd(&base[27 - c], 1);
        g_rowof[pos] = n;
        g_pcnt[pos] = c;
        int j = 0;
#pragma unroll
        for (int k = 0; k < 27; k++) {
            int id = snbr[tid * 27 + k];
            if (id >= 0) { g_pairs[j * NP + pos] = (k << 20) | id; j++; }
        }
    }
}

// ---------------------------------------------------------------------------
// Submanifold 3x3x3 conv over CSR pairs. Thread = one sorted row, 16 couts.
// Loop only over the row's valid neighbors (warp trip counts uniform thanks
// to count-sorting). W in SMEM with padded k-stride to cap LDS conflicts.
// ---------------------------------------------------------------------------
__global__ __launch_bounds__(128) void conv_kernel(
    const float* __restrict__ x, const float* __restrict__ W,
    float* __restrict__ y, int N, int NP, int statbase)
{
    __shared__ float Ws[27 * WSTRIDE];   // 27.8 KB, [k][c*16+o] at stride 264
    __shared__ float sstat[32];

    int tid = threadIdx.x;
    for (int i = tid; i < 27 * 256; i += 128)
        Ws[(i >> 8) * WSTRIDE + (i & 255)] = W[i];
    if (tid < 32) sstat[tid] = 0.f;
    __syncthreads();

    int i  = blockIdx.x * 128 + tid;
    bool vn = (i < N);
    int cnt  = vn ? g_pcnt[i] : 0;
    int nrow = vn ? g_rowof[i] : 0;

    int wm = cnt;
#pragma unroll
    for (int off = 16; off >= 1; off >>= 1)
        wm = max(wm, __shfl_xor_sync(0xffffffffu, wm, off));

    float4 a0 = make_float4(0.f, 0.f, 0.f, 0.f);
    float4 a1 = a0, a2 = a0, a3 = a0;

#define CSTEP(xc, cidx) {                                          \
        const float4* wp = (const float4*)(Wk + (cidx) * 16);      \
        float4 w0 = wp[0], w1 = wp[1], w2 = wp[2], w3 = wp[3];     \
        a0.x = fmaf(xc, w0.x, a0.x); a0.y = fmaf(xc, w0.y, a0.y);  \
        a0.z = fmaf(xc, w0.z, a0.z); a0.w = fmaf(xc, w0.w, a0.w);  \
        a1.x = fmaf(xc, w1.x, a1.x); a1.y = fmaf(xc, w1.y, a1.y);  \
        a1.z = fmaf(xc, w1.z, a1.z); a1.w = fmaf(xc, w1.w, a1.w);  \
        a2.x = fmaf(xc, w2.x, a2.x); a2.y = fmaf(xc, w2.y, a2.y);  \
        a2.z = fmaf(xc, w2.z, a2.z); a2.w = fmaf(xc, w2.w, a2.w);  \
        a3.x = fmaf(xc, w3.x, a3.x); a3.y = fmaf(xc, w3.y, a3.y);  \
        a3.z = fmaf(xc, w3.z, a3.z); a3.w = fmaf(xc, w3.w, a3.w);  }

    for (int j = 0; j < wm; j++) {
        int pair = (j < cnt) ? g_pairs[j * NP + i] : -1;
        int k  = (pair >= 0) ? (pair >> 20) : 0;
        float4 v0, v1, v2, v3;
        if (pair >= 0) {
            const float4* xp = (const float4*)(x + (pair & 0xFFFFF) * 16);
            v0 = xp[0]; v1 = xp[1]; v2 = xp[2]; v3 = xp[3];
        } else {
            v0 = v1 = v2 = v3 = make_float4(0.f, 0.f, 0.f, 0.f);
        }
        const float* Wk = Ws + k * WSTRIDE;
        CSTEP(v0.x, 0)  CSTEP(v0.y, 1)  CSTEP(v0.z, 2)  CSTEP(v0.w, 3)
        CSTEP(v1.x, 4)  CSTEP(v1.y, 5)  CSTEP(v1.z, 6)  CSTEP(v1.w, 7)
        CSTEP(v2.x, 8)  CSTEP(v2.y, 9)  CSTEP(v2.z, 10) CSTEP(v2.w, 11)
        CSTEP(v3.x, 12) CSTEP(v3.y, 13) CSTEP(v3.z, 14) CSTEP(v3.w, 15)
    }
#undef CSTEP

    if (vn) {
        float4* yp = (float4*)(y + nrow * 16);
        yp[0] = a0; yp[1] = a1; yp[2] = a2; yp[3] = a3;
    }

    // ---- BN stats: per-channel butterfly, lane0 -> SMEM, block -> global ----
    float av[16] = {a0.x, a0.y, a0.z, a0.w, a1.x, a1.y, a1.z, a1.w,
                    a2.x, a2.y, a2.z, a2.w, a3.x, a3.y, a3.z, a3.w};
#pragma unroll
    for (int c = 0; c < 16; c++) {
        float s = av[c];
        float q = s * s;
#pragma unroll
        for (int off = 1; off < 32; off <<= 1) {
            s += __shfl_xor_sync(0xffffffffu, s, off);
            q += __shfl_xor_sync(0xffffffffu, q, off);
        }
        if ((tid & 31) == 0) {
            atomicAdd(&sstat[c], s);
            atomicAdd(&sstat[16 + c], q);
        }
    }
    __syncthreads();
    if (tid < 32) atomicAdd(&g_stats[statbase + tid], sstat[tid]);
}

// y0b = relu(bn0(y0)) elementwise (affine from g_stats base 0)
__global__ __launch_bounds__(256) void bnrelu_kernel(
    const float* __restrict__ yin, float* __restrict__ yout,
    const float* __restrict__ g, const float* __restrict__ b,
    int N, float invN)
{
    __shared__ float saff[32];
    int tid = threadIdx.x;
    if (tid < 16) {
        float mu  = g_stats[tid] * invN;
        float var = g_stats[16 + tid] * invN - mu * mu;
        float s   = g[tid] * rsqrtf(var + CEPS);
        saff[tid]      = s;
        saff[16 + tid] = b[tid] - mu * s;
    }
    __syncthreads();
    int i = blockIdx.x * 256 + tid;      // one float4 (4 channels) per thread
    if (i >= N * 4) return;
    int c4 = (i & 3) * 4;
    float4 v = *(const float4*)(yin + i * 4);
    v.x = fmaxf(fmaf(v.x, saff[c4 + 0], saff[16 + c4 + 0]), 0.f);
    v.y = fmaxf(fmaf(v.y, saff[c4 + 1], saff[16 + c4 + 1]), 0.f);
    v.z = fmaxf(fmaf(v.z, saff[c4 + 2], saff[16 + c4 + 2]), 0.f);
    v.w = fmaxf(fmaf(v.w, saff[c4 + 3], saff[16 + c4 + 3]), 0.f);
    *(float4*)(yout + i * 4) = v;
}

// tiny stats-zero kernel
__global__ void zero_stats_kernel() {
    if (threadIdx.x < 64) g_stats[threadIdx.x] = 0.f;
}

// t2 = f2 @ Wobo + bobo, atomicAdd-scatter into merged
__global__ __launch_bounds__(256) void fuse_t2_kernel(
    const float* __restrict__ f2, const float* __restrict__ Wobo,
    const float* __restrict__ bobo, const int* __restrict__ seg2, int N)
{
    __shared__ float Wo[256];
    __shared__ float sf[16 * 17];
    __shared__ float sb[16];
    int tid = threadIdx.x;
    Wo[tid] = Wobo[tid];
    if (tid < 16) sb[tid] = bobo[tid];
    int n0 = blockIdx.x * 16;
    if (tid < 64) {
        int r = tid >> 2, c4 = (tid & 3) * 4;
        float4 v = make_float4(0.f, 0.f, 0.f, 0.f);
        if (n0 + r < N) v = *(const float4*)(f2 + (n0 + r) * 16 + c4);
        sf[r * 17 + c4 + 0] = v.x; sf[r * 17 + c4 + 1] = v.y;
        sf[r * 17 + c4 + 2] = v.z; sf[r * 17 + c4 + 3] = v.w;
    }
    __syncthreads();
    int tx = tid & 15, ty = tid >> 4;
    int n = n0 + ty;
    if (n >= N) return;
    float acc = sb[tx];
#pragma unroll
    for (int c = 0; c < 16; c++)
        acc = fmaf(sf[ty * 17 + c], Wo[c * 16 + tx], acc);
    atomicAdd(&g_merged[seg2[n] * 16 + tx], acc);
}

// h = relu(bn1(y1)), atomicAdd-scatter into merged
__global__ __launch_bounds__(256) void fuse_h_kernel(
    const float* __restrict__ y1, const float* __restrict__ g1,
    const float* __restrict__ b1, const int* __restrict__ seg, int N, float invN)
{
    __shared__ float saff[32];
    int tid = threadIdx.x;
    if (tid < 16) {
        float mu  = g_stats[32 + tid] * invN;
        float var = g_stats[48 + tid] * invN - mu * mu;
        float s   = g1[tid] * rsqrtf(var + CEPS);
        saff[tid]      = s;
        saff[16 + tid] = b1[tid] - mu * s;
    }
    __syncthreads();
    int tx = tid & 15, ty = tid >> 4;
    int n = blockIdx.x * 16 + ty;
    if (n >= N) return;
    float h = fmaxf(fmaf(y1[n * 16 + tx], saff[tx], saff[16 + tx]), 0.f);
    atomicAdd(&g_merged[seg[n] * 16 + tx], h);
}

// out[u,:] = merged[u,:] @ Wf + bf.  32 rows x 128 cols per block.
__global__ __launch_bounds__(256) void out_kernel(
    const float* __restrict__ Wf, const float* __restrict__ bf,
    float* __restrict__ out, int U)
{
    __shared__ float Wfs[2048];
    __shared__ float sx[32 * 16];
    int tid = threadIdx.x;
    for (int i = tid; i < 2048; i += 256) Wfs[i] = Wf[i];
    int u0 = blockIdx.x * 32;
    if (tid < 128) {
        int r = tid >> 2, c4 = (tid & 3) * 4;
        float4 v = make_float4(0.f, 0.f, 0.f, 0.f);
        if (u0 + r < U) v = *(const float4*)(g_merged + (u0 + r) * 16 + c4);
        *(float4*)(sx + r * 16 + c4) = v;
    }
    __syncthreads();

    int cx = tid & 31, ry = tid >> 5;
    float4 bv = *(const float4*)(bf + cx * 4);
    float4 a0 = bv, a1 = bv, a2 = bv, a3 = bv;

#pragma unroll
    for (int c = 0; c < 16; c++) {
        float4 wv = *(const float4*)(Wfs + c * 128 + cx * 4);
        float x0 = sx[(ry * 4 + 0) * 16 + c];
        float x1 = sx[(ry * 4 + 1) * 16 + c];
        float x2 = sx[(ry * 4 + 2) * 16 + c];
        float x3 = sx[(ry * 4 + 3) * 16 + c];
        a0.x = fmaf(x0, wv.x, a0.x); a0.y = fmaf(x0, wv.y, a0.y);
        a0.z = fmaf(x0, wv.z, a0.z); a0.w = fmaf(x0, wv.w, a0.w);
        a1.x = fmaf(x1, wv.x, a1.x); a1.y = fmaf(x1, wv.y, a1.y);
        a1.z = fmaf(x1, wv.z, a1.z); a1.w = fmaf(x1, wv.w, a1.w);
        a2.x = fmaf(x2, wv.x, a2.x); a2.y = fmaf(x2, wv.y, a2.y);
        a2.z = fmaf(x2, wv.z, a2.z); a2.w = fmaf(x2, wv.w, a2.w);
        a3.x = fmaf(x3, wv.x, a3.x); a3.y = fmaf(x3, wv.y, a3.y);
        a3.z = fmaf(x3, wv.z, a3.z); a3.w = fmaf(x3, wv.w, a3.w);
    }

    int u = u0 + ry * 4;
    if (u + 0 < U) *(float4*)(out + (u + 0) * 128 + cx * 4) = a0;
    if (u + 1 < U) *(float4*)(out + (u + 1) * 128 + cx * 4) = a1;
    if (u + 2 < U) *(float4*)(out + (u + 2) * 128 + cx * 4) = a2;
    if (u + 3 < U) *(float4*)(out + (u + 3) * 128 + cx * 4) = a3;
}

extern "C" void kernel_launch(void* const* d_in, const int* in_sizes, int n_in,
                              void* d_out, int out_size)
{
    const float* vox  = (const float*)d_in[0];
    const float* f2   = (const float*)d_in[1];
    const float* W0   = (const float*)d_in[2];
    const float* g0   = (const float*)d_in[3];
    const float* b0   = (const float*)d_in[4];
    const float* W1   = (const float*)d_in[5];
    const float* g1   = (const float*)d_in[6];
    const float* b1   = (const float*)d_in[7];
    const float* Wobo = (const float*)d_in[8];
    const float* bobo = (const float*)d_in[9];
    const float* Wf   = (const float*)d_in[10];
    const float* bf   = (const float*)d_in[11];
    const int*   nbr  = (const int*)d_in[12];
    const int*   seg  = (const int*)d_in[13];

    int N  = in_sizes[0] / 16;
    int U  = out_size / 128;
    int NP = (N + 255) & ~255;

    void *p_merged, *p_y0, *p_y0b, *p_y1;
    cudaGetSymbolAddress(&p_merged, g_merged);
    cudaGetSymbolAddress(&p_y0,     g_y0);
    cudaGetSymbolAddress(&p_y0b,    g_y0b);
    cudaGetSymbolAddress(&p_y1,     g_y1);

    float invN = 1.0f / (float)N;
    int nblk = (N + 255) / 256;
    int cblocks = (N + 127) / 128;

    cudaMemsetAsync(p_merged, 0, (size_t)U * 16 * sizeof(float));
    zero_stats_kernel<<<1, 64>>>();
    count_kernel<<<nblk, 256>>>(nbr, N);
    prefix_kernel<<<1, 32>>>(nblk);
    build_kernel<<<nblk, 256>>>(nbr, N, NP);
    conv_kernel<<<cblocks, 128>>>(vox, W0, (float*)p_y0, N, NP, 0);
    bnrelu_kernel<<<(N * 4 + 255) / 256, 256>>>((const float*)p_y0,
                                                (float*)p_y0b, g0, b0,
                                                N, invN);
    conv_kernel<<<cblocks, 128>>>((const float*)p_y0b, W1,
                                  (float*)p_y1, N, NP, 32);
    fuse_h_kernel<<<(N + 15) / 16, 256>>>((const float*)p_y1, g1, b1,
                                          seg, N, invN);
    fuse_t2_kernel<<<(N + 15) / 16, 256>>>(f2, Wobo, bobo, seg + N, N);
    out_kernel<<<(U + 31) / 32, 256>>>(Wf, bf, (float*)d_out, U);
}